// round 13
// baseline (speedup 1.0000x reference)
#include <cuda_runtime.h>
#include <cuda_fp16.h>
#include <math.h>
#include <stdint.h>

// Problem constants
#define BB    32
#define TT    512
#define DIMV  512
#define QQ    8
#define CC    256
#define DD    256
#define HIDV  1024
#define MROWS (BB*TT)          // 16384
#define XR_N  (MROWS*DIMV)     // 8388608
#define IDX_N (MROWS*QQ)       // 131072

// ---------------- fp32 scratch ----------------
__device__ float g_xt [MROWS*DIMV];
__device__ float g_h0 [MROWS*HIDV];
__device__ float g_h1 [MROWS*HIDV];
__device__ float g_z  [MROWS*QQ*DD];
__device__ float g_logits[(size_t)QQ*MROWS*CC];
__device__ float g_emb[MROWS*DD];
__device__ int   g_code[MROWS*QQ];
__device__ float g_sum[8192];
__device__ float g_sumsq[8192];
__device__ float g_scale[2048];
__device__ float g_shift[2048];
__device__ float g_loss[1];

// ---------------- pre-split half2 buffers (u32 = 2 halves) ----------------
__device__ uint32_t g_xtH [MROWS*DIMV/2],  g_xtL [MROWS*DIMV/2];
__device__ uint32_t g_h0H [MROWS*HIDV/2],  g_h0L [MROWS*HIDV/2];
__device__ uint32_t g_h1H [MROWS*HIDV/2],  g_h1L [MROWS*HIDV/2];
__device__ uint32_t g_zH  [MROWS*QQ*DD/2], g_zL  [MROWS*QQ*DD/2];
__device__ uint32_t g_embH[MROWS*DD/2],    g_embL[MROWS*DD/2];
__device__ uint32_t g_wH  [3014656],       g_wL  [3014656];
// weight pool offsets (u32 units) — contiguous in split order
#define OFF_W0   0
#define OFF_W1   262144
#define OFF_WO   786432
#define OFF_CB   1835008
#define OFF_DW0  2097152
#define OFF_DW1  2228224
#define OFF_FW   2752512
#define W_TOTAL  3014656

// ======================= fp16x3 helpers =======================
#define INV2048 4.8828125e-4f

__device__ __forceinline__ void split2h(float a, float b, uint32_t& hi, uint32_t& lo) {
    __half ha = __float2half_rn(a), hb = __float2half_rn(b);
    float ra = (a - __half2float(ha)) * 2048.0f;
    float rb = (b - __half2float(hb)) * 2048.0f;
    __half2 h = __halves2half2(ha, hb);
    __half2 l = __halves2half2(__float2half_rn(ra), __float2half_rn(rb));
    hi = *(uint32_t*)&h;
    lo = *(uint32_t*)&l;
}

__device__ __forceinline__ void mma16(float* d, const uint32_t* a, const uint32_t* b) {
    asm volatile(
        "mma.sync.aligned.m16n8k16.row.col.f32.f16.f16.f32 "
        "{%0,%1,%2,%3}, {%4,%5,%6,%7}, {%8,%9}, {%0,%1,%2,%3};"
        : "+f"(d[0]), "+f"(d[1]), "+f"(d[2]), "+f"(d[3])
        : "r"(a[0]), "r"(a[1]), "r"(a[2]), "r"(a[3]), "r"(b[0]), "r"(b[1]));
}

__device__ __forceinline__ void ldsm4(uint32_t& r0, uint32_t& r1, uint32_t& r2, uint32_t& r3,
                                      uint32_t addr) {
    asm volatile("ldmatrix.sync.aligned.m8n8.x4.shared.b16 {%0,%1,%2,%3}, [%4];"
                 : "=r"(r0), "=r"(r1), "=r"(r2), "=r"(r3) : "r"(addr));
}

__device__ __forceinline__ void cpasync16(uint32_t smem_addr, const uint32_t* gptr) {
    asm volatile("cp.async.cg.shared.global [%0], [%1], 16;"
                 :: "r"(smem_addr), "l"(gptr) : "memory");
}

// ---------------- batched weight split: all 7 matrices in one launch ----------------
__global__ void split_all(const float* __restrict__ w0,  const float* __restrict__ w1,
                          const float* __restrict__ wo,  const float* __restrict__ cbp,
                          const float* __restrict__ dw0, const float* __restrict__ dw1,
                          const float* __restrict__ fw,
                          uint32_t* __restrict__ H, uint32_t* __restrict__ L) {
    size_t i = (size_t)blockIdx.x * 256 + threadIdx.x;
    const float* src; size_t base;
    if      (i < OFF_W1)  { src = w0;  base = OFF_W0;  }
    else if (i < OFF_WO)  { src = w1;  base = OFF_W1;  }
    else if (i < OFF_CB)  { src = wo;  base = OFF_WO;  }
    else if (i < OFF_DW0) { src = cbp; base = OFF_CB;  }
    else if (i < OFF_DW1) { src = dw0; base = OFF_DW0; }
    else if (i < OFF_FW)  { src = dw1; base = OFF_DW1; }
    else                  { src = fw;  base = OFF_FW;  }
    float2 v = *(const float2*)(src + 2 * (i - base));
    uint32_t h, l;
    split2h(v.x, v.y, h, l);
    H[i] = h; L[i] = l;
}

// ---------------- init: zero stats + loss ----------------
__global__ void init_stats_kernel(float* __restrict__ sum, float* __restrict__ sumsq,
                                  float* __restrict__ loss) {
    int i = blockIdx.x * 256 + threadIdx.x;
    if (i < 8192) { sum[i] = 0.f; sumsq[i] = 0.f; }
    if (i == 0) loss[0] = 0.f;
}

// ======================= pre-split fp16x3 GEMM =======================
// 512 threads / 16 warps, warp tile 32x32. cp.async 4-stage pipeline, prefetch
// depth 3, staging hoisted ahead of the mma burst (fill overlaps compute).
// Stage layout: stage s at s*4*SP u32; within: AH | AL | WH | WL.
#define KC      32
#define P2      20
#define SP      (128*P2)          // 2560 u32 per buffer
#define STAGES  4
#define STAGE_U (4*SP)            // u32 per stage
#define GSMEM2  (STAGES*STAGE_U*4)   // 163840 bytes

__global__ __launch_bounds__(512, 1)
void gemm_h(const uint32_t* __restrict__ AH, const uint32_t* __restrict__ AL,
            int lda2, long long aQ2,
            const uint32_t* __restrict__ WH, const uint32_t* __restrict__ WL,
            int ldw2, long long wQ2,
            const float* __restrict__ bias,
            float* __restrict__ C, int ldc, long long cQ,
            uint32_t* __restrict__ CH, uint32_t* __restrict__ CL, int ldc2,
            int K,
            float* __restrict__ statSum, float* __restrict__ statSumsq,
            const float* __restrict__ ref, float* __restrict__ lossAcc)
{
    extern __shared__ uint32_t smu[];
    __shared__ float s_red[16];

    const int tid  = threadIdx.x;
    const int lane = tid & 31;
    const int wid  = tid >> 5;
    const int wm   = wid >> 2;         // 0..3 (32-row slab)
    const int wn   = wid & 3;          // 0..3 (32-col slab)
    const int m0   = blockIdx.y * 128;
    const int n0   = blockIdx.x * 128;
    const int q    = blockIdx.z;
    AH += (size_t)q * aQ2;  AL += (size_t)q * aQ2;
    WH += (size_t)q * wQ2;  WL += (size_t)q * wQ2;
    C  += (size_t)q * cQ;

    const int row = tid >> 2;          // staging row 0..127
    const int seg = (tid & 3) * 4;     // staging u32 segment (0,4,8,12)

    const uint32_t smemBase = (uint32_t)__cvta_generic_to_shared(smu);
    const int g  = lane >> 3;
    const int lr = lane & 7;
    const uint32_t aOff = ((uint32_t)((wm * 32 + (g & 1) * 8 + lr) * P2 + (g >> 1) * 4)) * 4;
    const uint32_t bOff = ((uint32_t)(2 * SP + (wn * 32 + (g >> 1) * 8 + lr) * P2 + (g & 1) * 4)) * 4;

    float acc [2][4][4];
    float acc2[2][4][4];
#pragma unroll
    for (int i = 0; i < 2; i++)
#pragma unroll
        for (int j = 0; j < 4; j++)
#pragma unroll
            for (int r = 0; r < 4; r++) { acc[i][j][r] = 0.f; acc2[i][j][r] = 0.f; }

    const int nk = K / KC;             // chunk = 16 u32 per row

    const uint32_t* gAH = AH + (size_t)(m0 + row) * lda2 + seg;
    const uint32_t* gAL = AL + (size_t)(m0 + row) * lda2 + seg;
    const uint32_t* gWH = WH + (size_t)(n0 + row) * ldw2 + seg;
    const uint32_t* gWL = WL + (size_t)(n0 + row) * ldw2 + seg;
    const uint32_t stOff = (uint32_t)(row * P2 + seg) * 4;

    auto stage_chunk = [&](int c) {
        const int k2 = c * 16;
        const uint32_t sb = smemBase + (uint32_t)((c % STAGES) * STAGE_U) * 4 + stOff;
        cpasync16(sb,              gAH + k2);
        cpasync16(sb + SP * 4,     gAL + k2);
        cpasync16(sb + 2 * SP * 4, gWH + k2);
        cpasync16(sb + 3 * SP * 4, gWL + k2);
        asm volatile("cp.async.commit_group;" ::: "memory");
    };

    // prefetch depth 3
    stage_chunk(0);
    if (nk > 1) stage_chunk(1);
    if (nk > 2) stage_chunk(2);

    for (int c = 0; c < nk; c++) {
        // groups committed beyond c: min(2, nk-1-c)
        if (c + 3 <= nk)      asm volatile("cp.async.wait_group 2;" ::: "memory");
        else if (c + 2 == nk) asm volatile("cp.async.wait_group 1;" ::: "memory");
        else                  asm volatile("cp.async.wait_group 0;" ::: "memory");
        __syncthreads();

        // hoist next staging ABOVE the mma burst — fill overlaps compute.
        // buffer (c+3)%4 == (c-1)%4, whose readers all passed the barrier above.
        if (c + 3 < nk) stage_chunk(c + 3);

        const uint32_t sb4 = (uint32_t)((c % STAGES) * STAGE_U) * 4;

#pragma unroll
        for (int ks = 0; ks < 2; ks++) {
            uint32_t ah[2][4], al[2][4], bh[4][2], bl[4][2];
            const uint32_t aA = smemBase + sb4 + aOff + ks * 32;
            const uint32_t bA = smemBase + sb4 + bOff + ks * 32;
#pragma unroll
            for (int mi = 0; mi < 2; mi++) {
                ldsm4(ah[mi][0], ah[mi][1], ah[mi][2], ah[mi][3], aA + mi * (16 * P2 * 4));
                ldsm4(al[mi][0], al[mi][1], al[mi][2], al[mi][3],
                      aA + mi * (16 * P2 * 4) + SP * 4);
            }
#pragma unroll
            for (int p = 0; p < 2; p++) {
                ldsm4(bh[p * 2][0], bh[p * 2][1], bh[p * 2 + 1][0], bh[p * 2 + 1][1],
                      bA + p * (16 * P2 * 4));
                ldsm4(bl[p * 2][0], bl[p * 2][1], bl[p * 2 + 1][0], bl[p * 2 + 1][1],
                      bA + p * (16 * P2 * 4) + SP * 4);
            }
            // pass 1: hi*hi -> acc
#pragma unroll
            for (int mi = 0; mi < 2; mi++)
#pragma unroll
                for (int ni = 0; ni < 4; ni++)
                    mma16(acc[mi][ni], ah[mi], bh[ni]);
            // pass 2: hi*lo -> acc2
#pragma unroll
            for (int mi = 0; mi < 2; mi++)
#pragma unroll
                for (int ni = 0; ni < 4; ni++)
                    mma16(acc2[mi][ni], ah[mi], bl[ni]);
            // pass 3: lo*hi -> acc2
#pragma unroll
            for (int mi = 0; mi < 2; mi++)
#pragma unroll
                for (int ni = 0; ni < 4; ni++)
                    mma16(acc2[mi][ni], al[mi], bh[ni]);
        }
    }

    // epilogue
    float lsum = 0.f;
    float sc[4][2], ssc[4][2];
#pragma unroll
    for (int ni = 0; ni < 4; ni++) { sc[ni][0] = sc[ni][1] = 0.f; ssc[ni][0] = ssc[ni][1] = 0.f; }

#pragma unroll
    for (int mi = 0; mi < 2; mi++) {
#pragma unroll
        for (int h = 0; h < 2; h++) {
            const size_t m = (size_t)(m0 + wm * 32 + mi * 16 + (lane >> 2) + h * 8);
#pragma unroll
            for (int ni = 0; ni < 4; ni++) {
                const int col = n0 + wn * 32 + ni * 8 + 2 * (lane & 3);
                float v0 = acc[mi][ni][2 * h + 0] + acc2[mi][ni][2 * h + 0] * INV2048;
                float v1 = acc[mi][ni][2 * h + 1] + acc2[mi][ni][2 * h + 1] * INV2048;
                if (bias) { v0 += __ldg(bias + col); v1 += __ldg(bias + col + 1); }
                if (statSum) {
                    sc[ni][0] += v0; ssc[ni][0] += v0 * v0;
                    sc[ni][1] += v1; ssc[ni][1] += v1 * v1;
                }
                if (ref) {
                    float d0 = v0 - __ldg(ref + m * ldc + col);
                    float d1 = v1 - __ldg(ref + m * ldc + col + 1);
                    lsum += d0 * d0 + d1 * d1;
                }
                *(float2*)(C + m * ldc + col) = make_float2(v0, v1);
                if (CH) {
                    uint32_t hh, ll;
                    split2h(v0, v1, hh, ll);
                    size_t o2 = m * ldc2 + (size_t)(col >> 1);
                    CH[o2] = hh; CL[o2] = ll;
                }
            }
        }
    }
    if (statSum) {
#pragma unroll
        for (int ni = 0; ni < 4; ni++) {
            float s0 = sc[ni][0], s1 = sc[ni][1], q0 = ssc[ni][0], q1 = ssc[ni][1];
#pragma unroll
            for (int off = 4; off < 32; off <<= 1) {
                s0 += __shfl_down_sync(0xffffffffu, s0, off);
                s1 += __shfl_down_sync(0xffffffffu, s1, off);
                q0 += __shfl_down_sync(0xffffffffu, q0, off);
                q1 += __shfl_down_sync(0xffffffffu, q1, off);
            }
            if (lane < 4) {
                int col = n0 + wn * 32 + ni * 8 + 2 * lane;
                atomicAdd(&statSum[col],       s0);
                atomicAdd(&statSum[col + 1],   s1);
                atomicAdd(&statSumsq[col],     q0);
                atomicAdd(&statSumsq[col + 1], q1);
            }
        }
    }
    if (lossAcc) {
#pragma unroll
        for (int off = 16; off; off >>= 1)
            lsum += __shfl_down_sync(0xffffffffu, lsum, off);
        if (lane == 0) s_red[wid] = lsum;
        __syncthreads();
        if (tid == 0) {
            float s = 0.f;
#pragma unroll
            for (int w = 0; w < 16; w++) s += s_red[w];
            atomicAdd(lossAcc, s);
        }
    }
}

// ---------------- transpose + fused xt split ----------------
__global__ void transpose_kernel(const float* __restrict__ x, float* __restrict__ xt,
                                 uint32_t* __restrict__ xtH, uint32_t* __restrict__ xtL) {
    __shared__ float tile[32][33];
    int b  = blockIdx.z;
    int t0 = blockIdx.x * 32;
    int d0 = blockIdx.y * 32;
    int tx = threadIdx.x, ty = threadIdx.y;
    const float* xb = x  + (size_t)b * DIMV * TT;
    float*      xtb = xt + (size_t)b * TT * DIMV;
#pragma unroll
    for (int j = 0; j < 32; j += 8)
        tile[ty + j][tx] = xb[(size_t)(d0 + ty + j) * TT + t0 + tx];
    __syncthreads();
#pragma unroll
    for (int j = 0; j < 32; j += 8) {
        xtb[(size_t)(t0 + ty + j) * DIMV + d0 + tx] = tile[tx][ty + j];
        if ((tx & 1) == 0) {
            uint32_t h, l;
            split2h(tile[tx][ty + j], tile[tx + 1][ty + j], h, l);
            size_t o2 = ((size_t)b * TT + t0 + ty + j) * (DIMV / 2) + ((d0 + tx) >> 1);
            xtH[o2] = h; xtL[o2] = l;
        }
    }
}

// ---------------- BN kernels ----------------
__global__ void colstats_kernel(const float* __restrict__ X, int N,
                                float* __restrict__ sum, float* __restrict__ sumsq) {
    int col = blockIdx.x * 32 + threadIdx.x;
    int r0  = blockIdx.y * 2048;
    float s = 0.f, ss = 0.f;
    for (int r = r0 + threadIdx.y; r < r0 + 2048; r += 8) {
        float v = X[(size_t)r * N + col];
        s += v; ss += v * v;
    }
    __shared__ float sh [8][32];
    __shared__ float sh2[8][32];
    sh [threadIdx.y][threadIdx.x] = s;
    sh2[threadIdx.y][threadIdx.x] = ss;
    __syncthreads();
    if (threadIdx.y == 0) {
#pragma unroll
        for (int w = 1; w < 8; w++) { s += sh[w][threadIdx.x]; ss += sh2[w][threadIdx.x]; }
        atomicAdd(&sum[col], s);
        atomicAdd(&sumsq[col], ss);
    }
}

__global__ void bnparams_kernel(const float* __restrict__ sum, const float* __restrict__ sumsq,
                                const float* __restrict__ g, const float* __restrict__ be, int N) {
    int c = blockIdx.x * 128 + threadIdx.x;
    if (c >= N) return;
    const float invM = 1.0f / (float)MROWS;
    float m   = sum[c] * invM;
    float var = sumsq[c] * invM - m * m;
    float sc  = g[c] * rsqrtf(var + 1e-5f);
    g_scale[c] = sc;
    g_shift[c] = be[c] - m * sc;
}

// apply BN (+relu) and emit split halves directly
__global__ void bnapply_split(const float* __restrict__ X,
                              uint32_t* __restrict__ H, uint32_t* __restrict__ L,
                              int mask, int relu) {
    size_t i = (size_t)blockIdx.x * 256 + threadIdx.x;
    float2 v = *(const float2*)(X + 2 * i);
    int c0 = (int)(2 * i) & mask;
    float a = v.x * g_scale[c0] + g_shift[c0];
    float b = v.y * g_scale[c0 + 1] + g_shift[c0 + 1];
    if (relu) { a = fmaxf(a, 0.f); b = fmaxf(b, 0.f); }
    uint32_t h, l;
    split2h(a, b, h, l);
    H[i] = h; L[i] = l;
}

// ---------------- gumbel ----------------
__device__ __forceinline__ float gumbel_of(float uu) {
    uu = fminf(fmaxf(uu, 1e-9f), 1.0f);
    return -logf(-logf(uu) + 1e-20f);
}

// ---------------- dual argmax with exact fp32 refinement ----------------
__global__ __launch_bounds__(256) void argmax_kernel(
    const float* __restrict__ logits, const float* __restrict__ z,
    const float* __restrict__ cb, const float* __restrict__ u,
    const float* __restrict__ lt, float* __restrict__ idx_out, int* __restrict__ code_out)
{
    const int q    = blockIdx.y;
    const int row  = blockIdx.x * 8 + (threadIdx.x >> 5);
    const int lane = threadIdx.x & 31;
    const float scale = expf(-__ldg(lt + q));
    const float* lrow = logits + ((size_t)q * MROWS + row) * CC;
    const float* urow = u + ((size_t)row * QQ + q) * CC;

    float lv[8], nn[8];
    bool exR[8], exN[8];
#pragma unroll
    for (int it = 0; it < 8; it++) {
        int c = it * 32 + lane;
        lv[it] = __ldg(lrow + c);
        nn[it] = lv[it] * scale + gumbel_of(__ldg(urow + c));
        exR[it] = false; exN[it] = false;
    }

    int candR[3], candN[3];
#pragma unroll
    for (int r = 0; r < 3; r++) {
        float bv = -INFINITY; int bi = 1 << 30;
#pragma unroll
        for (int it = 0; it < 8; it++)
            if (!exR[it] && (lv[it] > bv || (lv[it] == bv && it * 32 + lane < bi))) {
                bv = lv[it]; bi = it * 32 + lane;
            }
#pragma unroll
        for (int off = 16; off; off >>= 1) {
            float ov = __shfl_down_sync(0xffffffffu, bv, off);
            int   oi = __shfl_down_sync(0xffffffffu, bi, off);
            if (ov > bv || (ov == bv && oi < bi)) { bv = ov; bi = oi; }
        }
        bi = __shfl_sync(0xffffffffu, bi, 0);
        candR[r] = bi;
        if ((bi & 31) == lane) exR[bi >> 5] = true;

        bv = -INFINITY; bi = 1 << 30;
#pragma unroll
        for (int it = 0; it < 8; it++)
            if (!exN[it] && (nn[it] > bv || (nn[it] == bv && it * 32 + lane < bi))) {
                bv = nn[it]; bi = it * 32 + lane;
            }
#pragma unroll
        for (int off = 16; off; off >>= 1) {
            float ov = __shfl_down_sync(0xffffffffu, bv, off);
            int   oi = __shfl_down_sync(0xffffffffu, bi, off);
            if (ov > bv || (ov == bv && oi < bi)) { bv = ov; bi = oi; }
        }
        bi = __shfl_sync(0xffffffffu, bi, 0);
        candN[r] = bi;
        if ((bi & 31) == lane) exN[bi >> 5] = true;
    }

    const float* zrow = z + (size_t)row * (QQ * DD) + q * DD;
    float4 z0 = __ldg((const float4*)(zrow + lane * 8));
    float4 z1 = __ldg((const float4*)(zrow + lane * 8 + 4));
    float dR[3], dN[3];
#pragma unroll
    for (int r = 0; r < 3; r++) {
#pragma unroll
        for (int pass = 0; pass < 2; pass++) {
            int c = pass ? candN[r] : candR[r];
            const float* crow = cb + ((size_t)q * CC + c) * DD;
            float4 c0 = __ldg((const float4*)(crow + lane * 8));
            float4 c1 = __ldg((const float4*)(crow + lane * 8 + 4));
            float d = z0.x * c0.x + z0.y * c0.y + z0.z * c0.z + z0.w * c0.w
                    + z1.x * c1.x + z1.y * c1.y + z1.z * c1.z + z1.w * c1.w;
#pragma unroll
            for (int off = 16; off; off >>= 1)
                d += __shfl_down_sync(0xffffffffu, d, off);
            if (pass) dN[r] = d; else dR[r] = d;
        }
    }

    if (lane == 0) {
        int ri = candR[0]; float rv = dR[0];
#pragma unroll
        for (int r = 1; r < 3; r++)
            if (dR[r] > rv || (dR[r] == rv && candR[r] < ri)) { rv = dR[r]; ri = candR[r]; }
        int ni = candN[0];
        float nv = dN[0] * scale + gumbel_of(__ldg(urow + candN[0]));
#pragma unroll
        for (int r = 1; r < 3; r++) {
            float s = dN[r] * scale + gumbel_of(__ldg(urow + candN[r]));
            if (s > nv || (s == nv && candN[r] < ni)) { nv = s; ni = candN[r]; }
        }
        size_t o = (size_t)row * QQ + q;
        idx_out[o]  = (float)ri;
        code_out[o] = ni;
    }
}

// ---------------- embedding gather ----------------
__global__ void embed_kernel(const int* __restrict__ code, const float* __restrict__ cb,
                             float* __restrict__ emb) {
    int bt = blockIdx.x;
    int d  = threadIdx.x;
    float s = 0.f;
#pragma unroll
    for (int q = 0; q < QQ; q++) {
        int ci = code[bt * QQ + q];
        s += cb[((size_t)(q * CC + ci)) * DD + d];
    }
    emb[(size_t)bt * DD + d] = s;
}

__global__ void finalize_loss_kernel(float* __restrict__ out) {
    out[0] = g_loss[0] * (1.0f / (float)XR_N);
}

// ---------------- host orchestration ----------------
extern "C" void kernel_launch(void* const* d_in, const int* in_sizes, int n_in,
                              void* d_out, int out_size) {
    const float* x       = (const float*)d_in[0];
    const float* u       = (const float*)d_in[1];
    const float* cb      = (const float*)d_in[2];
    const float* lt      = (const float*)d_in[3];
    const float* enc_w0  = (const float*)d_in[4];
    const float* enc_b0  = (const float*)d_in[5];
    const float* enc_g0  = (const float*)d_in[6];
    const float* enc_be0 = (const float*)d_in[7];
    const float* enc_w1  = (const float*)d_in[8];
    const float* enc_b1  = (const float*)d_in[9];
    const float* enc_g1  = (const float*)d_in[10];
    const float* enc_be1 = (const float*)d_in[11];
    const float* enc_wo  = (const float*)d_in[12];
    const float* enc_bo  = (const float*)d_in[13];
    const float* dec_g   = (const float*)d_in[14];
    const float* dec_be  = (const float*)d_in[15];
    const float* dec_w0  = (const float*)d_in[16];
    const float* dec_b0  = (const float*)d_in[17];
    const float* dec_g0  = (const float*)d_in[18];
    const float* dec_be0 = (const float*)d_in[19];
    const float* dec_w1  = (const float*)d_in[20];
    const float* dec_b1  = (const float*)d_in[21];
    const float* dec_g1  = (const float*)d_in[22];
    const float* dec_be1 = (const float*)d_in[23];
    const float* fin_w   = (const float*)d_in[24];
    const float* fin_b   = (const float*)d_in[25];
    float* out = (float*)d_out;

    float *xt, *h0, *h1, *z, *logits, *emb, *sum, *sumsq, *loss;
    int* code;
    uint32_t *xtH, *xtL, *h0H, *h0L, *h1H, *h1L, *zH, *zL, *embH, *embL, *wH, *wL;
    cudaGetSymbolAddress((void**)&xt,    g_xt);
    cudaGetSymbolAddress((void**)&h0,    g_h0);
    cudaGetSymbolAddress((void**)&h1,    g_h1);
    cudaGetSymbolAddress((void**)&z,     g_z);
    cudaGetSymbolAddress((void**)&logits,g_logits);
    cudaGetSymbolAddress((void**)&emb,   g_emb);
    cudaGetSymbolAddress((void**)&code,  g_code);
    cudaGetSymbolAddress((void**)&sum,   g_sum);
    cudaGetSymbolAddress((void**)&sumsq, g_sumsq);
    cudaGetSymbolAddress((void**)&loss,  g_loss);
    cudaGetSymbolAddress((void**)&xtH,   g_xtH);   cudaGetSymbolAddress((void**)&xtL, g_xtL);
    cudaGetSymbolAddress((void**)&h0H,   g_h0H);   cudaGetSymbolAddress((void**)&h0L, g_h0L);
    cudaGetSymbolAddress((void**)&h1H,   g_h1H);   cudaGetSymbolAddress((void**)&h1L, g_h1L);
    cudaGetSymbolAddress((void**)&zH,    g_zH);    cudaGetSymbolAddress((void**)&zL,  g_zL);
    cudaGetSymbolAddress((void**)&embH,  g_embH);  cudaGetSymbolAddress((void**)&embL,g_embL);
    cudaGetSymbolAddress((void**)&wH,    g_wH);    cudaGetSymbolAddress((void**)&wL,  g_wL);

    cudaFuncSetAttribute(gemm_h, cudaFuncAttributeMaxDynamicSharedMemorySize, GSMEM2);

    // stat slices (zeroed once below)
    float* S_E0  = sum;        float* Q_E0  = sumsq;
    float* S_E1  = sum + 1024; float* Q_E1  = sumsq + 1024;
    float* S_DE  = sum + 2048; float* Q_DE  = sumsq + 2048;
    float* S_D0  = sum + 2304; float* Q_D0  = sumsq + 2304;
    float* S_D1  = sum + 3328; float* Q_D1  = sumsq + 3328;

    init_stats_kernel<<<32, 256>>>(sum, sumsq, loss);

    // ---- all weight splits in one launch ----
    split_all<<<W_TOTAL / 256, 256>>>(enc_w0, enc_w1, enc_wo, cb, dec_w0, dec_w1, fin_w, wH, wL);

    // ---- encoder ----
    transpose_kernel<<<dim3(TT / 32, DIMV / 32, BB), dim3(32, 8)>>>(x, xt, xtH, xtL);

    gemm_h<<<dim3(HIDV / 128, MROWS / 128), 512, GSMEM2>>>(
        xtH, xtL, DIMV / 2, 0, wH + OFF_W0, wL + OFF_W0, DIMV / 2, 0,
        enc_b0, h0, HIDV, 0, nullptr, nullptr, 0, DIMV, S_E0, Q_E0, nullptr, nullptr);
    bnparams_kernel<<<HIDV / 128, 128>>>(S_E0, Q_E0, enc_g0, enc_be0, HIDV);
    bnapply_split<<<(unsigned)((size_t)MROWS * HIDV / 512), 256>>>(h0, h0H, h0L, HIDV - 1, 1);

    gemm_h<<<dim3(HIDV / 128, MROWS / 128), 512, GSMEM2>>>(
        h0H, h0L, HIDV / 2, 0, wH + OFF_W1, wL + OFF_W1, HIDV / 2, 0,
        enc_b1, h1, HIDV, 0, nullptr, nullptr, 0, HIDV, S_E1, Q_E1, nullptr, nullptr);
    bnparams_kernel<<<HIDV / 128, 128>>>(S_E1, Q_E1, enc_g1, enc_be1, HIDV);
    bnapply_split<<<(unsigned)((size_t)MROWS * HIDV / 512), 256>>>(h1, h1H, h1L, HIDV - 1, 1);

    // enc_wo: fp32 z + split halves out
    gemm_h<<<dim3((QQ * DD) / 128, MROWS / 128), 512, GSMEM2>>>(
        h1H, h1L, HIDV / 2, 0, wH + OFF_WO, wL + OFF_WO, HIDV / 2, 0,
        enc_bo, z, QQ * DD, 0, zH, zL, QQ * DD / 2, HIDV, nullptr, nullptr, nullptr, nullptr);

    // ---- logits (per-q block-diagonal) + argmax + embed ----
    gemm_h<<<dim3(CC / 128, MROWS / 128, QQ), 512, GSMEM2>>>(
        zH, zL, QQ * DD / 2, DD / 2,
        wH + OFF_CB, wL + OFF_CB, DD / 2, (long long)CC * DD / 2,
        nullptr, logits, CC, (long long)MROWS * CC,
        nullptr, nullptr, 0, DD, nullptr, nullptr, nullptr, nullptr);
    argmax_kernel<<<dim3(MROWS / 8, QQ), 256>>>(logits, z, cb, u, lt, out + XR_N, code);
    embed_kernel<<<MROWS, DD>>>(code, cb, emb);

    // ---- decoder ----
    colstats_kernel<<<dim3(DD / 32, 8), dim3(32, 8)>>>(emb, DD, S_DE, Q_DE);
    bnparams_kernel<<<DD / 128, 128>>>(S_DE, Q_DE, dec_g, dec_be, DD);
    bnapply_split<<<(unsigned)((size_t)MROWS * DD / 512), 256>>>(emb, embH, embL, DD - 1, 0);

    gemm_h<<<dim3(HIDV / 128, MROWS / 128), 512, GSMEM2>>>(
        embH, embL, DD / 2, 0, wH + OFF_DW0, wL + OFF_DW0, DD / 2, 0,
        dec_b0, h0, HIDV, 0, nullptr, nullptr, 0, DD, S_D0, Q_D0, nullptr, nullptr);
    bnparams_kernel<<<HIDV / 128, 128>>>(S_D0, Q_D0, dec_g0, dec_be0, HIDV);
    bnapply_split<<<(unsigned)((size_t)MROWS * HIDV / 512), 256>>>(h0, h0H, h0L, HIDV - 1, 1);

    gemm_h<<<dim3(HIDV / 128, MROWS / 128), 512, GSMEM2>>>(
        h0H, h0L, HIDV / 2, 0, wH + OFF_DW1, wL + OFF_DW1, HIDV / 2, 0,
        dec_b1, h1, HIDV, 0, nullptr, nullptr, 0, HIDV, S_D1, Q_D1, nullptr, nullptr);
    bnparams_kernel<<<HIDV / 128, 128>>>(S_D1, Q_D1, dec_g1, dec_be1, HIDV);
    bnapply_split<<<(unsigned)((size_t)MROWS * HIDV / 512), 256>>>(h1, h1H, h1L, HIDV - 1, 1);

    // ---- final linear + fused MSE loss vs xt ----
    gemm_h<<<dim3(DIMV / 128, MROWS / 128), 512, GSMEM2>>>(
        h1H, h1L, HIDV / 2, 0, wH + OFF_FW, wL + OFF_FW, HIDV / 2, 0,
        fin_b, out, DIMV, 0, nullptr, nullptr, 0, HIDV, nullptr, nullptr, xt, loss);
    finalize_loss_kernel<<<1, 1>>>(out + XR_N + IDX_N);
}

// round 15
// speedup vs baseline: 1.2264x; 1.2264x over previous
#include <cuda_runtime.h>
#include <cuda_fp16.h>
#include <math.h>
#include <stdint.h>

// Problem constants
#define BB    32
#define TT    512
#define DIMV  512
#define QQ    8
#define CC    256
#define DD    256
#define HIDV  1024
#define MROWS (BB*TT)          // 16384
#define XR_N  (MROWS*DIMV)     // 8388608
#define IDX_N (MROWS*QQ)       // 131072

// ---------------- fp32 scratch ----------------
__device__ float g_xt [MROWS*DIMV];
__device__ float g_h0 [MROWS*HIDV];
__device__ float g_h1 [MROWS*HIDV];
__device__ float g_z  [MROWS*QQ*DD];
__device__ float g_logits[(size_t)QQ*MROWS*CC];
__device__ float g_emb[MROWS*DD];
__device__ int   g_code[MROWS*QQ];
__device__ float g_sum[8192];
__device__ float g_sumsq[8192];
__device__ float g_scale[2048];
__device__ float g_shift[2048];
__device__ float g_loss[1];

// ---------------- pre-split half2 buffers (u32 = 2 halves) ----------------
__device__ uint32_t g_xtH [MROWS*DIMV/2],  g_xtL [MROWS*DIMV/2];
__device__ uint32_t g_h0H [MROWS*HIDV/2],  g_h0L [MROWS*HIDV/2];
__device__ uint32_t g_h1H [MROWS*HIDV/2],  g_h1L [MROWS*HIDV/2];
__device__ uint32_t g_zH  [MROWS*QQ*DD/2], g_zL  [MROWS*QQ*DD/2];
__device__ uint32_t g_embH[MROWS*DD/2],    g_embL[MROWS*DD/2];
__device__ uint32_t g_wH  [3014656],       g_wL  [3014656];
// weight pool offsets (u32 units) — contiguous in split order
#define OFF_W0   0
#define OFF_W1   262144
#define OFF_WO   786432
#define OFF_CB   1835008
#define OFF_DW0  2097152
#define OFF_DW1  2228224
#define OFF_FW   2752512
#define W_TOTAL  3014656

// ======================= fp16x3 helpers =======================
#define INV2048 4.8828125e-4f

__device__ __forceinline__ void split2h(float a, float b, uint32_t& hi, uint32_t& lo) {
    __half ha = __float2half_rn(a), hb = __float2half_rn(b);
    float ra = (a - __half2float(ha)) * 2048.0f;
    float rb = (b - __half2float(hb)) * 2048.0f;
    __half2 h = __halves2half2(ha, hb);
    __half2 l = __halves2half2(__float2half_rn(ra), __float2half_rn(rb));
    hi = *(uint32_t*)&h;
    lo = *(uint32_t*)&l;
}

__device__ __forceinline__ void mma16(float* d, const uint32_t* a, const uint32_t* b) {
    asm volatile(
        "mma.sync.aligned.m16n8k16.row.col.f32.f16.f16.f32 "
        "{%0,%1,%2,%3}, {%4,%5,%6,%7}, {%8,%9}, {%0,%1,%2,%3};"
        : "+f"(d[0]), "+f"(d[1]), "+f"(d[2]), "+f"(d[3])
        : "r"(a[0]), "r"(a[1]), "r"(a[2]), "r"(a[3]), "r"(b[0]), "r"(b[1]));
}

__device__ __forceinline__ void ldsm4(uint32_t& r0, uint32_t& r1, uint32_t& r2, uint32_t& r3,
                                      uint32_t addr) {
    asm volatile("ldmatrix.sync.aligned.m8n8.x4.shared.b16 {%0,%1,%2,%3}, [%4];"
                 : "=r"(r0), "=r"(r1), "=r"(r2), "=r"(r3) : "r"(addr));
}

__device__ __forceinline__ void cpasync16(uint32_t smem_addr, const uint32_t* gptr) {
    asm volatile("cp.async.cg.shared.global [%0], [%1], 16;"
                 :: "r"(smem_addr), "l"(gptr) : "memory");
}

// ---------------- batched weight split: all 7 matrices in one launch ----------------
__global__ void split_all(const float* __restrict__ w0,  const float* __restrict__ w1,
                          const float* __restrict__ wo,  const float* __restrict__ cbp,
                          const float* __restrict__ dw0, const float* __restrict__ dw1,
                          const float* __restrict__ fw,
                          uint32_t* __restrict__ H, uint32_t* __restrict__ L) {
    size_t i = (size_t)blockIdx.x * 256 + threadIdx.x;
    const float* src; size_t base;
    if      (i < OFF_W1)  { src = w0;  base = OFF_W0;  }
    else if (i < OFF_WO)  { src = w1;  base = OFF_W1;  }
    else if (i < OFF_CB)  { src = wo;  base = OFF_WO;  }
    else if (i < OFF_DW0) { src = cbp; base = OFF_CB;  }
    else if (i < OFF_DW1) { src = dw0; base = OFF_DW0; }
    else if (i < OFF_FW)  { src = dw1; base = OFF_DW1; }
    else                  { src = fw;  base = OFF_FW;  }
    float2 v = *(const float2*)(src + 2 * (i - base));
    uint32_t h, l;
    split2h(v.x, v.y, h, l);
    H[i] = h; L[i] = l;
}

// ---------------- init: zero stats + loss ----------------
__global__ void init_stats_kernel(float* __restrict__ sum, float* __restrict__ sumsq,
                                  float* __restrict__ loss) {
    int i = blockIdx.x * 256 + threadIdx.x;
    if (i < 8192) { sum[i] = 0.f; sumsq[i] = 0.f; }
    if (i == 0) loss[0] = 0.f;
}

// ======================= pre-split fp16x3 GEMM (R12 config) =======================
// 512 threads / 16 warps, warp tile 32x32, cp.async 3-stage.
// stage_chunk(c+2) issued BETWEEN the two k16 bursts (earlier async fill;
// buffer (c+2)%3 == (c-1)%3 whose readers passed this iteration's barrier).
#define KC      32
#define P2      20
#define SP      (128*P2)          // 2560 u32 per buffer
#define STAGES  3
#define STAGE_U (4*SP)            // u32 per stage
#define GSMEM2  (STAGES*STAGE_U*4)   // 122880 bytes

__global__ __launch_bounds__(512, 1)
void gemm_h(const uint32_t* __restrict__ AH, const uint32_t* __restrict__ AL,
            int lda2, long long aQ2,
            const uint32_t* __restrict__ WH, const uint32_t* __restrict__ WL,
            int ldw2, long long wQ2,
            const float* __restrict__ bias,
            float* __restrict__ C, int ldc, long long cQ,
            uint32_t* __restrict__ CH, uint32_t* __restrict__ CL, int ldc2,
            int K,
            float* __restrict__ statSum, float* __restrict__ statSumsq,
            const float* __restrict__ ref, float* __restrict__ lossAcc)
{
    extern __shared__ uint32_t smu[];
    __shared__ float s_red[16];

    const int tid  = threadIdx.x;
    const int lane = tid & 31;
    const int wid  = tid >> 5;
    const int wm   = wid >> 2;         // 0..3 (32-row slab)
    const int wn   = wid & 3;          // 0..3 (32-col slab)
    const int m0   = blockIdx.y * 128;
    const int n0   = blockIdx.x * 128;
    const int q    = blockIdx.z;
    AH += (size_t)q * aQ2;  AL += (size_t)q * aQ2;
    WH += (size_t)q * wQ2;  WL += (size_t)q * wQ2;
    C  += (size_t)q * cQ;

    const int row = tid >> 2;          // staging row 0..127
    const int seg = (tid & 3) * 4;     // staging u32 segment (0,4,8,12)

    const uint32_t smemBase = (uint32_t)__cvta_generic_to_shared(smu);
    const int g  = lane >> 3;
    const int lr = lane & 7;
    const uint32_t aOff = ((uint32_t)((wm * 32 + (g & 1) * 8 + lr) * P2 + (g >> 1) * 4)) * 4;
    const uint32_t bOff = ((uint32_t)(2 * SP + (wn * 32 + (g >> 1) * 8 + lr) * P2 + (g & 1) * 4)) * 4;

    float acc [2][4][4];
    float acc2[2][4][4];
#pragma unroll
    for (int i = 0; i < 2; i++)
#pragma unroll
        for (int j = 0; j < 4; j++)
#pragma unroll
            for (int r = 0; r < 4; r++) { acc[i][j][r] = 0.f; acc2[i][j][r] = 0.f; }

    const int nk = K / KC;             // chunk = 16 u32 per row

    const uint32_t* gAH = AH + (size_t)(m0 + row) * lda2 + seg;
    const uint32_t* gAL = AL + (size_t)(m0 + row) * lda2 + seg;
    const uint32_t* gWH = WH + (size_t)(n0 + row) * ldw2 + seg;
    const uint32_t* gWL = WL + (size_t)(n0 + row) * ldw2 + seg;
    const uint32_t stOff = (uint32_t)(row * P2 + seg) * 4;

    auto stage_chunk = [&](int c) {
        const int k2 = c * 16;
        const uint32_t sb = smemBase + (uint32_t)((c % STAGES) * STAGE_U) * 4 + stOff;
        cpasync16(sb,              gAH + k2);
        cpasync16(sb + SP * 4,     gAL + k2);
        cpasync16(sb + 2 * SP * 4, gWH + k2);
        cpasync16(sb + 3 * SP * 4, gWL + k2);
        asm volatile("cp.async.commit_group;" ::: "memory");
    };

    stage_chunk(0);
    if (nk > 1) stage_chunk(1);

    for (int c = 0; c < nk; c++) {
        if (c < nk - 1) asm volatile("cp.async.wait_group 1;" ::: "memory");
        else            asm volatile("cp.async.wait_group 0;" ::: "memory");
        __syncthreads();

        const uint32_t sb4 = (uint32_t)((c % STAGES) * STAGE_U) * 4;

#pragma unroll
        for (int ks = 0; ks < 2; ks++) {
            uint32_t ah[2][4], al[2][4], bh[4][2], bl[4][2];
            const uint32_t aA = smemBase + sb4 + aOff + ks * 32;
            const uint32_t bA = smemBase + sb4 + bOff + ks * 32;
#pragma unroll
            for (int mi = 0; mi < 2; mi++) {
                ldsm4(ah[mi][0], ah[mi][1], ah[mi][2], ah[mi][3], aA + mi * (16 * P2 * 4));
                ldsm4(al[mi][0], al[mi][1], al[mi][2], al[mi][3],
                      aA + mi * (16 * P2 * 4) + SP * 4);
            }
#pragma unroll
            for (int p = 0; p < 2; p++) {
                ldsm4(bh[p * 2][0], bh[p * 2][1], bh[p * 2 + 1][0], bh[p * 2 + 1][1],
                      bA + p * (16 * P2 * 4));
                ldsm4(bl[p * 2][0], bl[p * 2][1], bl[p * 2 + 1][0], bl[p * 2 + 1][1],
                      bA + p * (16 * P2 * 4) + SP * 4);
            }
            // pass 1: hi*hi -> acc
#pragma unroll
            for (int mi = 0; mi < 2; mi++)
#pragma unroll
                for (int ni = 0; ni < 4; ni++)
                    mma16(acc[mi][ni], ah[mi], bh[ni]);
            // pass 2: hi*lo -> acc2
#pragma unroll
            for (int mi = 0; mi < 2; mi++)
#pragma unroll
                for (int ni = 0; ni < 4; ni++)
                    mma16(acc2[mi][ni], ah[mi], bl[ni]);
            // pass 3: lo*hi -> acc2
#pragma unroll
            for (int mi = 0; mi < 2; mi++)
#pragma unroll
                for (int ni = 0; ni < 4; ni++)
                    mma16(acc2[mi][ni], al[mi], bh[ni]);

            // mid-burst async fill for chunk c+2 (after first k16 burst)
            if (ks == 0 && c + 2 < nk) stage_chunk(c + 2);
        }
    }

    // epilogue
    float lsum = 0.f;
    float sc[4][2], ssc[4][2];
#pragma unroll
    for (int ni = 0; ni < 4; ni++) { sc[ni][0] = sc[ni][1] = 0.f; ssc[ni][0] = ssc[ni][1] = 0.f; }

#pragma unroll
    for (int mi = 0; mi < 2; mi++) {
#pragma unroll
        for (int h = 0; h < 2; h++) {
            const size_t m = (size_t)(m0 + wm * 32 + mi * 16 + (lane >> 2) + h * 8);
#pragma unroll
            for (int ni = 0; ni < 4; ni++) {
                const int col = n0 + wn * 32 + ni * 8 + 2 * (lane & 3);
                float v0 = acc[mi][ni][2 * h + 0] + acc2[mi][ni][2 * h + 0] * INV2048;
                float v1 = acc[mi][ni][2 * h + 1] + acc2[mi][ni][2 * h + 1] * INV2048;
                if (bias) { v0 += __ldg(bias + col); v1 += __ldg(bias + col + 1); }
                if (statSum) {
                    sc[ni][0] += v0; ssc[ni][0] += v0 * v0;
                    sc[ni][1] += v1; ssc[ni][1] += v1 * v1;
                }
                if (ref) {
                    float d0 = v0 - __ldg(ref + m * ldc + col);
                    float d1 = v1 - __ldg(ref + m * ldc + col + 1);
                    lsum += d0 * d0 + d1 * d1;
                }
                *(float2*)(C + m * ldc + col) = make_float2(v0, v1);
                if (CH) {
                    uint32_t hh, ll;
                    split2h(v0, v1, hh, ll);
                    size_t o2 = m * ldc2 + (size_t)(col >> 1);
                    CH[o2] = hh; CL[o2] = ll;
                }
            }
        }
    }
    if (statSum) {
#pragma unroll
        for (int ni = 0; ni < 4; ni++) {
            float s0 = sc[ni][0], s1 = sc[ni][1], q0 = ssc[ni][0], q1 = ssc[ni][1];
#pragma unroll
            for (int off = 4; off < 32; off <<= 1) {
                s0 += __shfl_down_sync(0xffffffffu, s0, off);
                s1 += __shfl_down_sync(0xffffffffu, s1, off);
                q0 += __shfl_down_sync(0xffffffffu, q0, off);
                q1 += __shfl_down_sync(0xffffffffu, q1, off);
            }
            if (lane < 4) {
                int col = n0 + wn * 32 + ni * 8 + 2 * lane;
                atomicAdd(&statSum[col],       s0);
                atomicAdd(&statSum[col + 1],   s1);
                atomicAdd(&statSumsq[col],     q0);
                atomicAdd(&statSumsq[col + 1], q1);
            }
        }
    }
    if (lossAcc) {
#pragma unroll
        for (int off = 16; off; off >>= 1)
            lsum += __shfl_down_sync(0xffffffffu, lsum, off);
        if (lane == 0) s_red[wid] = lsum;
        __syncthreads();
        if (tid == 0) {
            float s = 0.f;
#pragma unroll
            for (int w = 0; w < 16; w++) s += s_red[w];
            atomicAdd(lossAcc, s);
        }
    }
}

// ---------------- transpose + fused xt split ----------------
__global__ void transpose_kernel(const float* __restrict__ x, float* __restrict__ xt,
                                 uint32_t* __restrict__ xtH, uint32_t* __restrict__ xtL) {
    __shared__ float tile[32][33];
    int b  = blockIdx.z;
    int t0 = blockIdx.x * 32;
    int d0 = blockIdx.y * 32;
    int tx = threadIdx.x, ty = threadIdx.y;
    const float* xb = x  + (size_t)b * DIMV * TT;
    float*      xtb = xt + (size_t)b * TT * DIMV;
#pragma unroll
    for (int j = 0; j < 32; j += 8)
        tile[ty + j][tx] = xb[(size_t)(d0 + ty + j) * TT + t0 + tx];
    __syncthreads();
#pragma unroll
    for (int j = 0; j < 32; j += 8) {
        xtb[(size_t)(t0 + ty + j) * DIMV + d0 + tx] = tile[tx][ty + j];
        if ((tx & 1) == 0) {
            uint32_t h, l;
            split2h(tile[tx][ty + j], tile[tx + 1][ty + j], h, l);
            size_t o2 = ((size_t)b * TT + t0 + ty + j) * (DIMV / 2) + ((d0 + tx) >> 1);
            xtH[o2] = h; xtL[o2] = l;
        }
    }
}

// ---------------- BN kernels ----------------
__global__ void colstats_kernel(const float* __restrict__ X, int N,
                                float* __restrict__ sum, float* __restrict__ sumsq) {
    int col = blockIdx.x * 32 + threadIdx.x;
    int r0  = blockIdx.y * 2048;
    float s = 0.f, ss = 0.f;
    for (int r = r0 + threadIdx.y; r < r0 + 2048; r += 8) {
        float v = X[(size_t)r * N + col];
        s += v; ss += v * v;
    }
    __shared__ float sh [8][32];
    __shared__ float sh2[8][32];
    sh [threadIdx.y][threadIdx.x] = s;
    sh2[threadIdx.y][threadIdx.x] = ss;
    __syncthreads();
    if (threadIdx.y == 0) {
#pragma unroll
        for (int w = 1; w < 8; w++) { s += sh[w][threadIdx.x]; ss += sh2[w][threadIdx.x]; }
        atomicAdd(&sum[col], s);
        atomicAdd(&sumsq[col], ss);
    }
}

__global__ void bnparams_kernel(const float* __restrict__ sum, const float* __restrict__ sumsq,
                                const float* __restrict__ g, const float* __restrict__ be, int N) {
    int c = blockIdx.x * 128 + threadIdx.x;
    if (c >= N) return;
    const float invM = 1.0f / (float)MROWS;
    float m   = sum[c] * invM;
    float var = sumsq[c] * invM - m * m;
    float sc  = g[c] * rsqrtf(var + 1e-5f);
    g_scale[c] = sc;
    g_shift[c] = be[c] - m * sc;
}

// apply BN (+relu) and emit split halves directly
__global__ void bnapply_split(const float* __restrict__ X,
                              uint32_t* __restrict__ H, uint32_t* __restrict__ L,
                              int mask, int relu) {
    size_t i = (size_t)blockIdx.x * 256 + threadIdx.x;
    float2 v = *(const float2*)(X + 2 * i);
    int c0 = (int)(2 * i) & mask;
    float a = v.x * g_scale[c0] + g_shift[c0];
    float b = v.y * g_scale[c0 + 1] + g_shift[c0 + 1];
    if (relu) { a = fmaxf(a, 0.f); b = fmaxf(b, 0.f); }
    uint32_t h, l;
    split2h(a, b, h, l);
    H[i] = h; L[i] = l;
}

// ---------------- gumbel ----------------
__device__ __forceinline__ float gumbel_of(float uu) {
    uu = fminf(fmaxf(uu, 1e-9f), 1.0f);
    return -logf(-logf(uu) + 1e-20f);
}

// ---------------- dual argmax with exact fp32 refinement ----------------
__global__ __launch_bounds__(256) void argmax_kernel(
    const float* __restrict__ logits, const float* __restrict__ z,
    const float* __restrict__ cb, const float* __restrict__ u,
    const float* __restrict__ lt, float* __restrict__ idx_out, int* __restrict__ code_out)
{
    const int q    = blockIdx.y;
    const int row  = blockIdx.x * 8 + (threadIdx.x >> 5);
    const int lane = threadIdx.x & 31;
    const float scale = expf(-__ldg(lt + q));
    const float* lrow = logits + ((size_t)q * MROWS + row) * CC;
    const float* urow = u + ((size_t)row * QQ + q) * CC;

    float lv[8], nn[8];
    bool exR[8], exN[8];
#pragma unroll
    for (int it = 0; it < 8; it++) {
        int c = it * 32 + lane;
        lv[it] = __ldg(lrow + c);
        nn[it] = lv[it] * scale + gumbel_of(__ldg(urow + c));
        exR[it] = false; exN[it] = false;
    }

    int candR[3], candN[3];
#pragma unroll
    for (int r = 0; r < 3; r++) {
        float bv = -INFINITY; int bi = 1 << 30;
#pragma unroll
        for (int it = 0; it < 8; it++)
            if (!exR[it] && (lv[it] > bv || (lv[it] == bv && it * 32 + lane < bi))) {
                bv = lv[it]; bi = it * 32 + lane;
            }
#pragma unroll
        for (int off = 16; off; off >>= 1) {
            float ov = __shfl_down_sync(0xffffffffu, bv, off);
            int   oi = __shfl_down_sync(0xffffffffu, bi, off);
            if (ov > bv || (ov == bv && oi < bi)) { bv = ov; bi = oi; }
        }
        bi = __shfl_sync(0xffffffffu, bi, 0);
        candR[r] = bi;
        if ((bi & 31) == lane) exR[bi >> 5] = true;

        bv = -INFINITY; bi = 1 << 30;
#pragma unroll
        for (int it = 0; it < 8; it++)
            if (!exN[it] && (nn[it] > bv || (nn[it] == bv && it * 32 + lane < bi))) {
                bv = nn[it]; bi = it * 32 + lane;
            }
#pragma unroll
        for (int off = 16; off; off >>= 1) {
            float ov = __shfl_down_sync(0xffffffffu, bv, off);
            int   oi = __shfl_down_sync(0xffffffffu, bi, off);
            if (ov > bv || (ov == bv && oi < bi)) { bv = ov; bi = oi; }
        }
        bi = __shfl_sync(0xffffffffu, bi, 0);
        candN[r] = bi;
        if ((bi & 31) == lane) exN[bi >> 5] = true;
    }

    const float* zrow = z + (size_t)row * (QQ * DD) + q * DD;
    float4 z0 = __ldg((const float4*)(zrow + lane * 8));
    float4 z1 = __ldg((const float4*)(zrow + lane * 8 + 4));
    float dR[3], dN[3];
#pragma unroll
    for (int r = 0; r < 3; r++) {
#pragma unroll
        for (int pass = 0; pass < 2; pass++) {
            int c = pass ? candN[r] : candR[r];
            const float* crow = cb + ((size_t)q * CC + c) * DD;
            float4 c0 = __ldg((const float4*)(crow + lane * 8));
            float4 c1 = __ldg((const float4*)(crow + lane * 8 + 4));
            float d = z0.x * c0.x + z0.y * c0.y + z0.z * c0.z + z0.w * c0.w
                    + z1.x * c1.x + z1.y * c1.y + z1.z * c1.z + z1.w * c1.w;
#pragma unroll
            for (int off = 16; off; off >>= 1)
                d += __shfl_down_sync(0xffffffffu, d, off);
            if (pass) dN[r] = d; else dR[r] = d;
        }
    }

    if (lane == 0) {
        int ri = candR[0]; float rv = dR[0];
#pragma unroll
        for (int r = 1; r < 3; r++)
            if (dR[r] > rv || (dR[r] == rv && candR[r] < ri)) { rv = dR[r]; ri = candR[r]; }
        int ni = candN[0];
        float nv = dN[0] * scale + gumbel_of(__ldg(urow + candN[0]));
#pragma unroll
        for (int r = 1; r < 3; r++) {
            float s = dN[r] * scale + gumbel_of(__ldg(urow + candN[r]));
            if (s > nv || (s == nv && candN[r] < ni)) { nv = s; ni = candN[r]; }
        }
        size_t o = (size_t)row * QQ + q;
        idx_out[o]  = (float)ri;
        code_out[o] = ni;
    }
}

// ---------------- embedding gather ----------------
__global__ void embed_kernel(const int* __restrict__ code, const float* __restrict__ cb,
                             float* __restrict__ emb) {
    int bt = blockIdx.x;
    int d  = threadIdx.x;
    float s = 0.f;
#pragma unroll
    for (int q = 0; q < QQ; q++) {
        int ci = code[bt * QQ + q];
        s += cb[((size_t)(q * CC + ci)) * DD + d];
    }
    emb[(size_t)bt * DD + d] = s;
}

__global__ void finalize_loss_kernel(float* __restrict__ out) {
    out[0] = g_loss[0] * (1.0f / (float)XR_N);
}

// ---------------- host orchestration ----------------
extern "C" void kernel_launch(void* const* d_in, const int* in_sizes, int n_in,
                              void* d_out, int out_size) {
    const float* x       = (const float*)d_in[0];
    const float* u       = (const float*)d_in[1];
    const float* cb      = (const float*)d_in[2];
    const float* lt      = (const float*)d_in[3];
    const float* enc_w0  = (const float*)d_in[4];
    const float* enc_b0  = (const float*)d_in[5];
    const float* enc_g0  = (const float*)d_in[6];
    const float* enc_be0 = (const float*)d_in[7];
    const float* enc_w1  = (const float*)d_in[8];
    const float* enc_b1  = (const float*)d_in[9];
    const float* enc_g1  = (const float*)d_in[10];
    const float* enc_be1 = (const float*)d_in[11];
    const float* enc_wo  = (const float*)d_in[12];
    const float* enc_bo  = (const float*)d_in[13];
    const float* dec_g   = (const float*)d_in[14];
    const float* dec_be  = (const float*)d_in[15];
    const float* dec_w0  = (const float*)d_in[16];
    const float* dec_b0  = (const float*)d_in[17];
    const float* dec_g0  = (const float*)d_in[18];
    const float* dec_be0 = (const float*)d_in[19];
    const float* dec_w1  = (const float*)d_in[20];
    const float* dec_b1  = (const float*)d_in[21];
    const float* dec_g1  = (const float*)d_in[22];
    const float* dec_be1 = (const float*)d_in[23];
    const float* fin_w   = (const float*)d_in[24];
    const float* fin_b   = (const float*)d_in[25];
    float* out = (float*)d_out;

    float *xt, *h0, *h1, *z, *logits, *emb, *sum, *sumsq, *loss;
    int* code;
    uint32_t *xtH, *xtL, *h0H, *h0L, *h1H, *h1L, *zH, *zL, *embH, *embL, *wH, *wL;
    cudaGetSymbolAddress((void**)&xt,    g_xt);
    cudaGetSymbolAddress((void**)&h0,    g_h0);
    cudaGetSymbolAddress((void**)&h1,    g_h1);
    cudaGetSymbolAddress((void**)&z,     g_z);
    cudaGetSymbolAddress((void**)&logits,g_logits);
    cudaGetSymbolAddress((void**)&emb,   g_emb);
    cudaGetSymbolAddress((void**)&code,  g_code);
    cudaGetSymbolAddress((void**)&sum,   g_sum);
    cudaGetSymbolAddress((void**)&sumsq, g_sumsq);
    cudaGetSymbolAddress((void**)&loss,  g_loss);
    cudaGetSymbolAddress((void**)&xtH,   g_xtH);   cudaGetSymbolAddress((void**)&xtL, g_xtL);
    cudaGetSymbolAddress((void**)&h0H,   g_h0H);   cudaGetSymbolAddress((void**)&h0L, g_h0L);
    cudaGetSymbolAddress((void**)&h1H,   g_h1H);   cudaGetSymbolAddress((void**)&h1L, g_h1L);
    cudaGetSymbolAddress((void**)&zH,    g_zH);    cudaGetSymbolAddress((void**)&zL,  g_zL);
    cudaGetSymbolAddress((void**)&embH,  g_embH);  cudaGetSymbolAddress((void**)&embL,g_embL);
    cudaGetSymbolAddress((void**)&wH,    g_wH);    cudaGetSymbolAddress((void**)&wL,  g_wL);

    cudaFuncSetAttribute(gemm_h, cudaFuncAttributeMaxDynamicSharedMemorySize, GSMEM2);

    // stat slices (zeroed once below)
    float* S_E0  = sum;        float* Q_E0  = sumsq;
    float* S_E1  = sum + 1024; float* Q_E1  = sumsq + 1024;
    float* S_DE  = sum + 2048; float* Q_DE  = sumsq + 2048;
    float* S_D0  = sum + 2304; float* Q_D0  = sumsq + 2304;
    float* S_D1  = sum + 3328; float* Q_D1  = sumsq + 3328;

    init_stats_kernel<<<32, 256>>>(sum, sumsq, loss);

    // ---- all weight splits in one launch ----
    split_all<<<W_TOTAL / 256, 256>>>(enc_w0, enc_w1, enc_wo, cb, dec_w0, dec_w1, fin_w, wH, wL);

    // ---- encoder ----
    transpose_kernel<<<dim3(TT / 32, DIMV / 32, BB), dim3(32, 8)>>>(x, xt, xtH, xtL);

    gemm_h<<<dim3(HIDV / 128, MROWS / 128), 512, GSMEM2>>>(
        xtH, xtL, DIMV / 2, 0, wH + OFF_W0, wL + OFF_W0, DIMV / 2, 0,
        enc_b0, h0, HIDV, 0, nullptr, nullptr, 0, DIMV, S_E0, Q_E0, nullptr, nullptr);
    bnparams_kernel<<<HIDV / 128, 128>>>(S_E0, Q_E0, enc_g0, enc_be0, HIDV);
    bnapply_split<<<(unsigned)((size_t)MROWS * HIDV / 512), 256>>>(h0, h0H, h0L, HIDV - 1, 1);

    gemm_h<<<dim3(HIDV / 128, MROWS / 128), 512, GSMEM2>>>(
        h0H, h0L, HIDV / 2, 0, wH + OFF_W1, wL + OFF_W1, HIDV / 2, 0,
        enc_b1, h1, HIDV, 0, nullptr, nullptr, 0, HIDV, S_E1, Q_E1, nullptr, nullptr);
    bnparams_kernel<<<HIDV / 128, 128>>>(S_E1, Q_E1, enc_g1, enc_be1, HIDV);
    bnapply_split<<<(unsigned)((size_t)MROWS * HIDV / 512), 256>>>(h1, h1H, h1L, HIDV - 1, 1);

    // enc_wo: fp32 z + split halves out
    gemm_h<<<dim3((QQ * DD) / 128, MROWS / 128), 512, GSMEM2>>>(
        h1H, h1L, HIDV / 2, 0, wH + OFF_WO, wL + OFF_WO, HIDV / 2, 0,
        enc_bo, z, QQ * DD, 0, zH, zL, QQ * DD / 2, HIDV, nullptr, nullptr, nullptr, nullptr);

    // ---- logits (per-q block-diagonal, full fp16x3) + argmax + embed ----
    gemm_h<<<dim3(CC / 128, MROWS / 128, QQ), 512, GSMEM2>>>(
        zH, zL, QQ * DD / 2, DD / 2,
        wH + OFF_CB, wL + OFF_CB, DD / 2, (long long)CC * DD / 2,
        nullptr, logits, CC, (long long)MROWS * CC,
        nullptr, nullptr, 0, DD, nullptr, nullptr, nullptr, nullptr);
    argmax_kernel<<<dim3(MROWS / 8, QQ), 256>>>(logits, z, cb, u, lt, out + XR_N, code);
    embed_kernel<<<MROWS, DD>>>(code, cb, emb);

    // ---- decoder ----
    colstats_kernel<<<dim3(DD / 32, 8), dim3(32, 8)>>>(emb, DD, S_DE, Q_DE);
    bnparams_kernel<<<DD / 128, 128>>>(S_DE, Q_DE, dec_g, dec_be, DD);
    bnapply_split<<<(unsigned)((size_t)MROWS * DD / 512), 256>>>(emb, embH, embL, DD - 1, 0);

    gemm_h<<<dim3(HIDV / 128, MROWS / 128), 512, GSMEM2>>>(
        embH, embL, DD / 2, 0, wH + OFF_DW0, wL + OFF_DW0, DD / 2, 0,
        dec_b0, h0, HIDV, 0, nullptr, nullptr, 0, DD, S_D0, Q_D0, nullptr, nullptr);
    bnparams_kernel<<<HIDV / 128, 128>>>(S_D0, Q_D0, dec_g0, dec_be0, HIDV);
    bnapply_split<<<(unsigned)((size_t)MROWS * HIDV / 512), 256>>>(h0, h0H, h0L, HIDV - 1, 1);

    gemm_h<<<dim3(HIDV / 128, MROWS / 128), 512, GSMEM2>>>(
        h0H, h0L, HIDV / 2, 0, wH + OFF_DW1, wL + OFF_DW1, HIDV / 2, 0,
        dec_b1, h1, HIDV, 0, nullptr, nullptr, 0, HIDV, S_D1, Q_D1, nullptr, nullptr);
    bnparams_kernel<<<HIDV / 128, 128>>>(S_D1, Q_D1, dec_g1, dec_be1, HIDV);
    bnapply_split<<<(unsigned)((size_t)MROWS * HIDV / 512), 256>>>(h1, h1H, h1L, HIDV - 1, 1);

    // ---- final linear + fused MSE loss vs xt ----
    gemm_h<<<dim3(DIMV / 128, MROWS / 128), 512, GSMEM2>>>(
        h1H, h1L, HIDV / 2, 0, wH + OFF_FW, wL + OFF_FW, HIDV / 2, 0,
        fin_b, out, DIMV, 0, nullptr, nullptr, 0, HIDV, nullptr, nullptr, xt, loss);
    finalize_loss_kernel<<<1, 1>>>(out + XR_N + IDX_N);
}